// round 3
// baseline (speedup 1.0000x reference)
#include <cuda_runtime.h>
#include <cuda_bf16.h>

#define S_LEN 2048
#define HID   2048
#define NH    16
#define NKV   8
#define HD    128
#define QDIM  (NH * HD)    // 2048
#define KVDIM (NKV * HD)   // 1024
#define SCALE 0.08838834764831845f
#define EPS   1e-6f

// ---------------- scratch (device globals; no allocation allowed) ----------
__device__ float g_Q[S_LEN * QDIM];    // 16 MB
__device__ float g_K[S_LEN * KVDIM];   //  8 MB
__device__ float g_V[S_LEN * KVDIM];   //  8 MB
__device__ float g_AO[S_LEN * QDIM];   // 16 MB

// ---------------- SGEMM body: C[128 x 128] tile, BK=8, 8x8 microtile -------
__device__ __forceinline__ void gemm128(const float* __restrict__ A,
                                        const float* __restrict__ B,
                                        float* __restrict__ C,
                                        int N, int K, int cRow, int cCol)
{
    __shared__ float As[8][128];
    __shared__ float Bs[8][128];
    const int tid  = threadIdx.x;
    const int rA   = tid >> 1;            // 0..127
    const int cA   = (tid & 1) << 2;      // 0 or 4
    const int rB   = tid >> 5;            // 0..7
    const int cB   = (tid & 31) << 2;     // 0..124
    const int tRow = (tid >> 4) << 3;     // 0..120 step 8
    const int tCol = (tid & 15) << 3;     // 0..120 step 8

    const float* Aptr = A + (size_t)cRow * 128 * K;
    const float* Bptr = B + cCol * 128;

    float acc[8][8] = {};

    for (int k0 = 0; k0 < K; k0 += 8) {
        float4 a = *(const float4*)(Aptr + (size_t)rA * K + cA);
        As[cA + 0][rA] = a.x;
        As[cA + 1][rA] = a.y;
        As[cA + 2][rA] = a.z;
        As[cA + 3][rA] = a.w;
        *(float4*)(&Bs[rB][cB]) = *(const float4*)(Bptr + (size_t)rB * N + cB);
        __syncthreads();
        Aptr += 8;
        Bptr += (size_t)8 * N;
        #pragma unroll
        for (int k = 0; k < 8; ++k) {
            float rm[8], rn[8];
            *(float4*)(&rm[0]) = *(const float4*)(&As[k][tRow]);
            *(float4*)(&rm[4]) = *(const float4*)(&As[k][tRow + 4]);
            *(float4*)(&rn[0]) = *(const float4*)(&Bs[k][tCol]);
            *(float4*)(&rn[4]) = *(const float4*)(&Bs[k][tCol + 4]);
            #pragma unroll
            for (int m = 0; m < 8; ++m)
                #pragma unroll
                for (int n = 0; n < 8; ++n)
                    acc[m][n] += rm[m] * rn[n];
        }
        __syncthreads();
    }

    float* Cp = C + (size_t)(cRow * 128 + tRow) * N + cCol * 128 + tCol;
    #pragma unroll
    for (int m = 0; m < 8; ++m) {
        *(float4*)(Cp + (size_t)m * N)     = make_float4(acc[m][0], acc[m][1], acc[m][2], acc[m][3]);
        *(float4*)(Cp + (size_t)m * N + 4) = make_float4(acc[m][4], acc[m][5], acc[m][6], acc[m][7]);
    }
}

// ---------------- fused QKV projection ------------------------------------
__global__ void __launch_bounds__(256) gemm_qkv_kernel(const float* __restrict__ hs,
                                                       const float* __restrict__ wq,
                                                       const float* __restrict__ wk,
                                                       const float* __restrict__ wv)
{
    int z = blockIdx.z;
    if (z == 0) {
        gemm128(hs, wq, g_Q, QDIM, HID, blockIdx.y, blockIdx.x);
    } else if (z == 1) {
        if (blockIdx.x >= KVDIM / 128) return;
        gemm128(hs, wk, g_K, KVDIM, HID, blockIdx.y, blockIdx.x);
    } else {
        if (blockIdx.x >= KVDIM / 128) return;
        gemm128(hs, wv, g_V, KVDIM, HID, blockIdx.y, blockIdx.x);
    }
}

// ---------------- output projection ----------------------------------------
__global__ void __launch_bounds__(256) gemm_out_kernel(const float* __restrict__ wo,
                                                       float* __restrict__ out)
{
    gemm128(g_AO, wo, out, HID, QDIM, blockIdx.y, blockIdx.x);
}

// ---------------- RMSNorm + RoPE (in place on g_Q / g_K) -------------------
// grid (S, NH+NKV), block 128. SCALE folded into Q.
__global__ void __launch_bounds__(128) rmsnorm_rope_kernel(const float* __restrict__ cos_t,
                                                           const float* __restrict__ sin_t,
                                                           const float* __restrict__ qw,
                                                           const float* __restrict__ kw)
{
    const int s = blockIdx.x;
    const int h = blockIdx.y;
    const int d = threadIdx.x;

    float* base;
    const float* w;
    float scl;
    if (h < NH) { base = g_Q + (size_t)s * QDIM + h * HD;        w = qw; scl = SCALE; }
    else        { base = g_K + (size_t)s * KVDIM + (h - NH) * HD; w = kw; scl = 1.0f; }

    float x = base[d];
    float v = x * x;
    #pragma unroll
    for (int off = 16; off; off >>= 1) v += __shfl_xor_sync(0xffffffffu, v, off);
    __shared__ float wsum[4];
    if ((d & 31) == 0) wsum[d >> 5] = v;
    __syncthreads();
    float rinv = rsqrtf((wsum[0] + wsum[1] + wsum[2] + wsum[3]) * (1.0f / HD) + EPS);

    float xn = x * rinv * w[d];
    __shared__ float sh[HD];
    sh[d] = xn;
    __syncthreads();
    float rot = (d < HD / 2) ? -sh[d + HD / 2] : sh[d - HD / 2];
    float c  = cos_t[(size_t)s * HD + d];
    float sn = sin_t[(size_t)s * HD + d];
    base[d] = (xn * c + rot * sn) * scl;
}

// ---------------- flash attention (fp32, causal, GQA) ----------------------
// grid (S/64, NH), 256 threads. Thread (ty,tx): ty=tid/16, tx=tid%16.
// Scores: 4 q-rows (ty*4..) x 4 k-cols (tx*4..). O: 4 q-rows x 8 dims (tx*8..).
#define BQ 64
#define BKT 64
#define KS_STR 129
#define PS_STR 65
#define FLASH_SMEM ((64*128 + 64*KS_STR + 64*128 + 64*PS_STR) * 4)

__global__ void __launch_bounds__(256) flash_kernel()
{
    const int h  = blockIdx.y;      // q head
    const int g  = h >> 1;          // kv head (NH/NKV = 2)
    const int qb = blockIdx.x;
    const int q0 = qb * BQ;
    const int tid = threadIdx.x;
    const int tx  = tid & 15;
    const int ty  = tid >> 4;
    const int iBase = ty * 4;
    const int jBase = tx * 4;
    const int dBase = tx * 8;

    extern __shared__ float smem[];
    float* Qs = smem;                 // [64][128]
    float* Ks = Qs + 64 * 128;        // [64][129]
    float* Vs = Ks + 64 * KS_STR;     // [64][128]
    float* Ps = Vs + 64 * 128;        // [64][65]

    // load Q tile (rows q0.., head h)
    for (int t = tid; t < 64 * 32; t += 256) {
        int r = t >> 5, c4 = (t & 31) << 2;
        *(float4*)(Qs + r * 128 + c4) =
            *(const float4*)(g_Q + (size_t)(q0 + r) * QDIM + h * HD + c4);
    }

    float m[4], l[4], o[4][8];
    #pragma unroll
    for (int i = 0; i < 4; ++i) {
        m[i] = -1e30f; l[i] = 0.f;
        #pragma unroll
        for (int d = 0; d < 8; ++d) o[i][d] = 0.f;
    }

    const int nkt = qb + 1;
    for (int kt = 0; kt < nkt; ++kt) {
        const int k0 = kt * BKT;
        __syncthreads();   // previous Ks/Vs/Ps consumers done (also covers Q load)
        for (int t = tid; t < 64 * 32; t += 256) {
            int r = t >> 5, c4 = (t & 31) << 2;
            const float* kp = g_K + (size_t)(k0 + r) * KVDIM + g * HD + c4;
            float4 kv = *(const float4*)kp;
            Ks[(size_t)r * KS_STR + c4 + 0] = kv.x;
            Ks[(size_t)r * KS_STR + c4 + 1] = kv.y;
            Ks[(size_t)r * KS_STR + c4 + 2] = kv.z;
            Ks[(size_t)r * KS_STR + c4 + 3] = kv.w;
            *(float4*)(Vs + r * 128 + c4) =
                *(const float4*)(g_V + (size_t)(k0 + r) * KVDIM + g * HD + c4);
        }
        __syncthreads();

        // S = Q K^T (scale already folded into Q)
        float sAcc[4][4] = {};
        #pragma unroll 4
        for (int d = 0; d < 128; ++d) {
            float qv[4], kv[4];
            #pragma unroll
            for (int i = 0; i < 4; ++i) qv[i] = Qs[(iBase + i) * 128 + d];
            #pragma unroll
            for (int j = 0; j < 4; ++j) kv[j] = Ks[(jBase + j) * KS_STR + d];
            #pragma unroll
            for (int i = 0; i < 4; ++i)
                #pragma unroll
                for (int j = 0; j < 4; ++j)
                    sAcc[i][j] += qv[i] * kv[j];
        }

        if (kt == qb) {   // diagonal tile: causal mask (k0 == q0 here)
            #pragma unroll
            for (int i = 0; i < 4; ++i)
                #pragma unroll
                for (int j = 0; j < 4; ++j)
                    if (jBase + j > iBase + i) sAcc[i][j] = -1e30f;
        }

        // online softmax
        #pragma unroll
        for (int i = 0; i < 4; ++i) {
            float lm = fmaxf(fmaxf(sAcc[i][0], sAcc[i][1]), fmaxf(sAcc[i][2], sAcc[i][3]));
            #pragma unroll
            for (int off = 8; off >= 1; off >>= 1)
                lm = fmaxf(lm, __shfl_xor_sync(0xffffffffu, lm, off));
            float mnew  = fmaxf(m[i], lm);
            float alpha = __expf(m[i] - mnew);
            float ps = 0.f;
            #pragma unroll
            for (int j = 0; j < 4; ++j) {
                float p = __expf(sAcc[i][j] - mnew);
                Ps[(iBase + i) * PS_STR + jBase + j] = p;
                ps += p;
            }
            #pragma unroll
            for (int off = 8; off >= 1; off >>= 1)
                ps += __shfl_xor_sync(0xffffffffu, ps, off);
            l[i] = l[i] * alpha + ps;
            m[i] = mnew;
            #pragma unroll
            for (int d = 0; d < 8; ++d) o[i][d] *= alpha;
        }
        __syncthreads();

        // O += P V
        #pragma unroll 2
        for (int j = 0; j < BKT; ++j) {
            float4 va = *(const float4*)(Vs + j * 128 + dBase);
            float4 vb = *(const float4*)(Vs + j * 128 + dBase + 4);
            #pragma unroll
            for (int i = 0; i < 4; ++i) {
                float p = Ps[(iBase + i) * PS_STR + j];
                o[i][0] += p * va.x; o[i][1] += p * va.y;
                o[i][2] += p * va.z; o[i][3] += p * va.w;
                o[i][4] += p * vb.x; o[i][5] += p * vb.y;
                o[i][6] += p * vb.z; o[i][7] += p * vb.w;
            }
        }
    }

    #pragma unroll
    for (int i = 0; i < 4; ++i) {
        float inv = 1.0f / l[i];
        float* dst = g_AO + (size_t)(q0 + iBase + i) * QDIM + h * HD + dBase;
        *(float4*)dst       = make_float4(o[i][0]*inv, o[i][1]*inv, o[i][2]*inv, o[i][3]*inv);
        *(float4*)(dst + 4) = make_float4(o[i][4]*inv, o[i][5]*inv, o[i][6]*inv, o[i][7]*inv);
    }
}

// ---------------- launch ----------------------------------------------------
extern "C" void kernel_launch(void* const* d_in, const int* in_sizes, int n_in,
                              void* d_out, int out_size)
{
    const float* hs    = (const float*)d_in[0];
    const float* cos_t = (const float*)d_in[1];
    const float* sin_t = (const float*)d_in[2];
    // d_in[3] = attention_mask (causal tril; applied analytically)
    const float* wq = (const float*)d_in[4];
    const float* wk = (const float*)d_in[5];
    const float* wv = (const float*)d_in[6];
    const float* wo = (const float*)d_in[7];
    const float* qw = (const float*)d_in[8];
    const float* kw = (const float*)d_in[9];
    float* out = (float*)d_out;

    cudaFuncSetAttribute(flash_kernel,
                         cudaFuncAttributeMaxDynamicSharedMemorySize, FLASH_SMEM);

    gemm_qkv_kernel<<<dim3(QDIM / 128, S_LEN / 128, 3), 256>>>(hs, wq, wk, wv);
    rmsnorm_rope_kernel<<<dim3(S_LEN, NH + NKV), 128>>>(cos_t, sin_t, qw, kw);
    flash_kernel<<<dim3(S_LEN / BQ, NH), 256, FLASH_SMEM>>>();
    gemm_out_kernel<<<dim3(HID / 128, S_LEN / 128), 256>>>(wo, out);
}

// round 4
// speedup vs baseline: 1.5305x; 1.5305x over previous
#include <cuda_runtime.h>
#include <cuda_bf16.h>

#define S_LEN 2048
#define HID   2048
#define NH    16
#define NKV   8
#define HD    128
#define QDIM  (NH * HD)    // 2048
#define KVDIM (NKV * HD)   // 1024
#define SCALE 0.08838834764831845f
#define EPS   1e-6f

// ---------------- scratch (device globals; no allocation allowed) ----------
__device__ float g_Q[S_LEN * QDIM];    // 16 MB
__device__ float g_K[S_LEN * KVDIM];   //  8 MB
__device__ float g_V[S_LEN * KVDIM];   //  8 MB
__device__ float g_AO[S_LEN * QDIM];   // 16 MB

// ---------------- tf32 helpers ----------------------------------------------
__device__ __forceinline__ unsigned f2tf(float x) {
    unsigned u;
    asm("cvt.rna.tf32.f32 %0, %1;" : "=r"(u) : "f"(x));
    return u;
}

// ---------------- tf32 tensor-core GEMM: 128x128 block tile -----------------
// 256 threads = 8 warps in 2(M) x 4(N); warp tile 64x32; mma m16n8k8 tf32.
// Smem K-major with row stride 136 floats (136 % 32 == 8) so fragment loads
// hit bank = 8*(k%4) + (lane>>2): conflict-free for a0..a3 / b0,b1 patterns.
#define KSTEP 32
#define SSTR  136

__device__ __forceinline__ void gemm_tf32(const float* __restrict__ A,
                                          const float* __restrict__ B,
                                          float* __restrict__ C,
                                          int N, int K, int cRow, int cCol)
{
    __shared__ float As[KSTEP * SSTR];   // [k][m], stride SSTR
    __shared__ float Bs[KSTEP * SSTR];   // [k][n], stride SSTR

    const int tid  = threadIdx.x;
    const int lane = tid & 31;
    const int w    = tid >> 5;
    const int warpM = (w >> 2) * 64;     // 0 or 64
    const int warpN = (w & 3) * 32;      // 0,32,64,96
    const int gr = lane >> 2;            // 0..7
    const int gc = lane & 3;             // 0..3

    const float* gA = A + (size_t)(cRow * 128) * K;
    const float* gB = B + (size_t)cCol * 128;

    float acc[4][4][4];
    #pragma unroll
    for (int mt = 0; mt < 4; ++mt)
        #pragma unroll
        for (int nt = 0; nt < 4; ++nt)
            #pragma unroll
            for (int i = 0; i < 4; ++i) acc[mt][nt][i] = 0.f;

    for (int k0 = 0; k0 < K; k0 += KSTEP) {
        __syncthreads();
        #pragma unroll
        for (int i = 0; i < 4; ++i) {
            int q = tid + 256 * i;
            // A tile: 128 rows x 32 k -> store transposed [k][m]
            int r  = q >> 3;
            int kc = (q & 7) << 2;
            float4 av = *(const float4*)(gA + (size_t)r * K + k0 + kc);
            As[(kc + 0) * SSTR + r] = __uint_as_float(f2tf(av.x));
            As[(kc + 1) * SSTR + r] = __uint_as_float(f2tf(av.y));
            As[(kc + 2) * SSTR + r] = __uint_as_float(f2tf(av.z));
            As[(kc + 3) * SSTR + r] = __uint_as_float(f2tf(av.w));
            // B tile: 32 k x 128 n -> store [k][n]
            int kb = q >> 5;
            int n4 = (q & 31) << 2;
            float4 bv = *(const float4*)(gB + (size_t)(k0 + kb) * N + n4);
            float4 bt;
            bt.x = __uint_as_float(f2tf(bv.x));
            bt.y = __uint_as_float(f2tf(bv.y));
            bt.z = __uint_as_float(f2tf(bv.z));
            bt.w = __uint_as_float(f2tf(bv.w));
            *(float4*)(Bs + kb * SSTR + n4) = bt;
        }
        __syncthreads();

        #pragma unroll
        for (int kk = 0; kk < 4; ++kk) {
            const int kb = kk * 8;
            unsigned a[4][4], b[4][2];
            #pragma unroll
            for (int mt = 0; mt < 4; ++mt) {
                int Rm = warpM + mt * 16 + gr;
                a[mt][0] = __float_as_uint(As[(kb + gc) * SSTR + Rm]);
                a[mt][1] = __float_as_uint(As[(kb + gc) * SSTR + Rm + 8]);
                a[mt][2] = __float_as_uint(As[(kb + 4 + gc) * SSTR + Rm]);
                a[mt][3] = __float_as_uint(As[(kb + 4 + gc) * SSTR + Rm + 8]);
            }
            #pragma unroll
            for (int nt = 0; nt < 4; ++nt) {
                int Cn = warpN + nt * 8 + gr;
                b[nt][0] = __float_as_uint(Bs[(kb + gc) * SSTR + Cn]);
                b[nt][1] = __float_as_uint(Bs[(kb + 4 + gc) * SSTR + Cn]);
            }
            #pragma unroll
            for (int mt = 0; mt < 4; ++mt)
                #pragma unroll
                for (int nt = 0; nt < 4; ++nt)
                    asm volatile(
                        "mma.sync.aligned.m16n8k8.row.col.f32.tf32.tf32.f32 "
                        "{%0,%1,%2,%3}, {%4,%5,%6,%7}, {%8,%9}, {%0,%1,%2,%3};"
                        : "+f"(acc[mt][nt][0]), "+f"(acc[mt][nt][1]),
                          "+f"(acc[mt][nt][2]), "+f"(acc[mt][nt][3])
                        : "r"(a[mt][0]), "r"(a[mt][1]), "r"(a[mt][2]), "r"(a[mt][3]),
                          "r"(b[nt][0]), "r"(b[nt][1]));
        }
    }

    // epilogue: c0,c1 at (row, 2c),(row, 2c+1); c2,c3 at row+8
    float* Cbase = C + (size_t)(cRow * 128 + warpM + gr) * N
                     + cCol * 128 + warpN + 2 * gc;
    #pragma unroll
    for (int mt = 0; mt < 4; ++mt)
        #pragma unroll
        for (int nt = 0; nt < 4; ++nt) {
            float* p = Cbase + (size_t)(mt * 16) * N + nt * 8;
            *(float2*)p                   = make_float2(acc[mt][nt][0], acc[mt][nt][1]);
            *(float2*)(p + (size_t)8 * N) = make_float2(acc[mt][nt][2], acc[mt][nt][3]);
        }
}

// ---------------- fused QKV projection --------------------------------------
__global__ void __launch_bounds__(256) gemm_qkv_kernel(const float* __restrict__ hs,
                                                       const float* __restrict__ wq,
                                                       const float* __restrict__ wk,
                                                       const float* __restrict__ wv)
{
    int z = blockIdx.z;
    if (z == 0) {
        gemm_tf32(hs, wq, g_Q, QDIM, HID, blockIdx.y, blockIdx.x);
    } else if (z == 1) {
        if (blockIdx.x >= KVDIM / 128) return;
        gemm_tf32(hs, wk, g_K, KVDIM, HID, blockIdx.y, blockIdx.x);
    } else {
        if (blockIdx.x >= KVDIM / 128) return;
        gemm_tf32(hs, wv, g_V, KVDIM, HID, blockIdx.y, blockIdx.x);
    }
}

// ---------------- output projection ------------------------------------------
__global__ void __launch_bounds__(256) gemm_out_kernel(const float* __restrict__ wo,
                                                       float* __restrict__ out)
{
    gemm_tf32(g_AO, wo, out, HID, QDIM, blockIdx.y, blockIdx.x);
}

// ---------------- RMSNorm + RoPE (in place on g_Q / g_K) --------------------
__global__ void __launch_bounds__(128) rmsnorm_rope_kernel(const float* __restrict__ cos_t,
                                                           const float* __restrict__ sin_t,
                                                           const float* __restrict__ qw,
                                                           const float* __restrict__ kw)
{
    const int s = blockIdx.x;
    const int h = blockIdx.y;
    const int d = threadIdx.x;

    float* base;
    const float* w;
    float scl;
    if (h < NH) { base = g_Q + (size_t)s * QDIM + h * HD;         w = qw; scl = SCALE; }
    else        { base = g_K + (size_t)s * KVDIM + (h - NH) * HD; w = kw; scl = 1.0f; }

    float x = base[d];
    float v = x * x;
    #pragma unroll
    for (int off = 16; off; off >>= 1) v += __shfl_xor_sync(0xffffffffu, v, off);
    __shared__ float wsum[4];
    if ((d & 31) == 0) wsum[d >> 5] = v;
    __syncthreads();
    float rinv = rsqrtf((wsum[0] + wsum[1] + wsum[2] + wsum[3]) * (1.0f / HD) + EPS);

    float xn = x * rinv * w[d];
    __shared__ float sh[HD];
    sh[d] = xn;
    __syncthreads();
    float rot = (d < HD / 2) ? -sh[d + HD / 2] : sh[d - HD / 2];
    float c  = cos_t[(size_t)s * HD + d];
    float sn = sin_t[(size_t)s * HD + d];
    base[d] = (xn * c + rot * sn) * scl;
}

// ---------------- flash attention (fp32, causal, GQA) -----------------------
#define BQ 64
#define BKT 64
#define KS_STR 129
#define PS_STR 65
#define FLASH_SMEM ((64*128 + 64*KS_STR + 64*128 + 64*PS_STR) * 4)

__global__ void __launch_bounds__(256) flash_kernel()
{
    const int h  = blockIdx.y;
    const int g  = h >> 1;
    const int qb = blockIdx.x;
    const int q0 = qb * BQ;
    const int tid = threadIdx.x;
    const int tx  = tid & 15;
    const int ty  = tid >> 4;
    const int iBase = ty * 4;
    const int jBase = tx * 4;
    const int dBase = tx * 8;

    extern __shared__ float smem[];
    float* Qs = smem;
    float* Ks = Qs + 64 * 128;
    float* Vs = Ks + 64 * KS_STR;
    float* Ps = Vs + 64 * 128;

    for (int t = tid; t < 64 * 32; t += 256) {
        int r = t >> 5, c4 = (t & 31) << 2;
        *(float4*)(Qs + r * 128 + c4) =
            *(const float4*)(g_Q + (size_t)(q0 + r) * QDIM + h * HD + c4);
    }

    float m[4], l[4], o[4][8];
    #pragma unroll
    for (int i = 0; i < 4; ++i) {
        m[i] = -1e30f; l[i] = 0.f;
        #pragma unroll
        for (int d = 0; d < 8; ++d) o[i][d] = 0.f;
    }

    const int nkt = qb + 1;
    for (int kt = 0; kt < nkt; ++kt) {
        const int k0 = kt * BKT;
        __syncthreads();
        for (int t = tid; t < 64 * 32; t += 256) {
            int r = t >> 5, c4 = (t & 31) << 2;
            const float* kp = g_K + (size_t)(k0 + r) * KVDIM + g * HD + c4;
            float4 kv = *(const float4*)kp;
            Ks[(size_t)r * KS_STR + c4 + 0] = kv.x;
            Ks[(size_t)r * KS_STR + c4 + 1] = kv.y;
            Ks[(size_t)r * KS_STR + c4 + 2] = kv.z;
            Ks[(size_t)r * KS_STR + c4 + 3] = kv.w;
            *(float4*)(Vs + r * 128 + c4) =
                *(const float4*)(g_V + (size_t)(k0 + r) * KVDIM + g * HD + c4);
        }
        __syncthreads();

        float sAcc[4][4] = {};
        #pragma unroll 4
        for (int d = 0; d < 128; ++d) {
            float qv[4], kv[4];
            #pragma unroll
            for (int i = 0; i < 4; ++i) qv[i] = Qs[(iBase + i) * 128 + d];
            #pragma unroll
            for (int j = 0; j < 4; ++j) kv[j] = Ks[(jBase + j) * KS_STR + d];
            #pragma unroll
            for (int i = 0; i < 4; ++i)
                #pragma unroll
                for (int j = 0; j < 4; ++j)
                    sAcc[i][j] += qv[i] * kv[j];
        }

        if (kt == qb) {
            #pragma unroll
            for (int i = 0; i < 4; ++i)
                #pragma unroll
                for (int j = 0; j < 4; ++j)
                    if (jBase + j > iBase + i) sAcc[i][j] = -1e30f;
        }

        #pragma unroll
        for (int i = 0; i < 4; ++i) {
            float lm = fmaxf(fmaxf(sAcc[i][0], sAcc[i][1]), fmaxf(sAcc[i][2], sAcc[i][3]));
            #pragma unroll
            for (int off = 8; off >= 1; off >>= 1)
                lm = fmaxf(lm, __shfl_xor_sync(0xffffffffu, lm, off));
            float mnew  = fmaxf(m[i], lm);
            float alpha = __expf(m[i] - mnew);
            float ps = 0.f;
            #pragma unroll
            for (int j = 0; j < 4; ++j) {
                float p = __expf(sAcc[i][j] - mnew);
                Ps[(iBase + i) * PS_STR + jBase + j] = p;
                ps += p;
            }
            #pragma unroll
            for (int off = 8; off >= 1; off >>= 1)
                ps += __shfl_xor_sync(0xffffffffu, ps, off);
            l[i] = l[i] * alpha + ps;
            m[i] = mnew;
            #pragma unroll
            for (int d = 0; d < 8; ++d) o[i][d] *= alpha;
        }
        __syncthreads();

        #pragma unroll 2
        for (int j = 0; j < BKT; ++j) {
            float4 va = *(const float4*)(Vs + j * 128 + dBase);
            float4 vb = *(const float4*)(Vs + j * 128 + dBase + 4);
            #pragma unroll
            for (int i = 0; i < 4; ++i) {
                float p = Ps[(iBase + i) * PS_STR + j];
                o[i][0] += p * va.x; o[i][1] += p * va.y;
                o[i][2] += p * va.z; o[i][3] += p * va.w;
                o[i][4] += p * vb.x; o[i][5] += p * vb.y;
                o[i][6] += p * vb.z; o[i][7] += p * vb.w;
            }
        }
    }

    #pragma unroll
    for (int i = 0; i < 4; ++i) {
        float inv = 1.0f / l[i];
        float* dst = g_AO + (size_t)(q0 + iBase + i) * QDIM + h * HD + dBase;
        *(float4*)dst       = make_float4(o[i][0]*inv, o[i][1]*inv, o[i][2]*inv, o[i][3]*inv);
        *(float4*)(dst + 4) = make_float4(o[i][4]*inv, o[i][5]*inv, o[i][6]*inv, o[i][7]*inv);
    }
}

// ---------------- launch ------------------------------------------------------
extern "C" void kernel_launch(void* const* d_in, const int* in_sizes, int n_in,
                              void* d_out, int out_size)
{
    const float* hs    = (const float*)d_in[0];
    const float* cos_t = (const float*)d_in[1];
    const float* sin_t = (const float*)d_in[2];
    // d_in[3] = attention_mask (causal tril; applied analytically)
    const float* wq = (const float*)d_in[4];
    const float* wk = (const float*)d_in[5];
    const float* wv = (const float*)d_in[6];
    const float* wo = (const float*)d_in[7];
    const float* qw = (const float*)d_in[8];
    const float* kw = (const float*)d_in[9];
    float* out = (float*)d_out;

    cudaFuncSetAttribute(flash_kernel,
                         cudaFuncAttributeMaxDynamicSharedMemorySize, FLASH_SMEM);

    gemm_qkv_kernel<<<dim3(QDIM / 128, S_LEN / 128, 3), 256>>>(hs, wq, wk, wv);
    rmsnorm_rope_kernel<<<dim3(S_LEN, NH + NKV), 128>>>(cos_t, sin_t, qw, kw);
    flash_kernel<<<dim3(S_LEN / BQ, NH), 256, FLASH_SMEM>>>();
    gemm_out_kernel<<<dim3(HID / 128, S_LEN / 128), 256>>>(wo, out);
}

// round 5
// speedup vs baseline: 2.6034x; 1.7010x over previous
#include <cuda_runtime.h>
#include <cuda_bf16.h>

#define S_LEN 2048
#define HID   2048
#define NH    16
#define NKV   8
#define HD    128
#define QDIM  (NH * HD)    // 2048
#define KVDIM (NKV * HD)   // 1024
#define SCALE 0.08838834764831845f
#define EPS   1e-6f

// ---------------- scratch (device globals; no allocation allowed) ----------
__device__ float g_Q[S_LEN * QDIM];    // 16 MB
__device__ float g_K[S_LEN * KVDIM];   //  8 MB
__device__ float g_V[S_LEN * KVDIM];   //  8 MB
__device__ float g_AO[S_LEN * QDIM];   // 16 MB

// ---------------- tf32 helpers ----------------------------------------------
__device__ __forceinline__ unsigned f2tf(float x) {
    unsigned u;
    asm("cvt.rna.tf32.f32 %0, %1;" : "=r"(u) : "f"(x));
    return u;
}
__device__ __forceinline__ float tfr(float x) { return __uint_as_float(f2tf(x)); }
__device__ __forceinline__ unsigned fu(float x) { return __float_as_uint(x); }

__device__ __forceinline__ void mma_tf32(float c[4], const unsigned a[4], const unsigned b[2]) {
    asm volatile(
        "mma.sync.aligned.m16n8k8.row.col.f32.tf32.tf32.f32 "
        "{%0,%1,%2,%3}, {%4,%5,%6,%7}, {%8,%9}, {%0,%1,%2,%3};"
        : "+f"(c[0]), "+f"(c[1]), "+f"(c[2]), "+f"(c[3])
        : "r"(a[0]), "r"(a[1]), "r"(a[2]), "r"(a[3]), "r"(b[0]), "r"(b[1]));
}

// ---------------- tf32 tensor-core GEMM: 128x128 block tile -----------------
#define KSTEP 32
#define SSTR  136

__device__ __forceinline__ void gemm_tf32(const float* __restrict__ A,
                                          const float* __restrict__ B,
                                          float* __restrict__ C,
                                          int N, int K, int cRow, int cCol)
{
    __shared__ float As[KSTEP * SSTR];   // [k][m]
    __shared__ float Bs[KSTEP * SSTR];   // [k][n]

    const int tid  = threadIdx.x;
    const int lane = tid & 31;
    const int w    = tid >> 5;
    const int warpM = (w >> 2) * 64;
    const int warpN = (w & 3) * 32;
    const int gr = lane >> 2;
    const int gc = lane & 3;

    const float* gA = A + (size_t)(cRow * 128) * K;
    const float* gB = B + (size_t)cCol * 128;

    float acc[4][4][4];
    #pragma unroll
    for (int mt = 0; mt < 4; ++mt)
        #pragma unroll
        for (int nt = 0; nt < 4; ++nt)
            #pragma unroll
            for (int i = 0; i < 4; ++i) acc[mt][nt][i] = 0.f;

    for (int k0 = 0; k0 < K; k0 += KSTEP) {
        __syncthreads();
        #pragma unroll
        for (int i = 0; i < 4; ++i) {
            int q = tid + 256 * i;
            int r  = q >> 3;
            int kc = (q & 7) << 2;
            float4 av = *(const float4*)(gA + (size_t)r * K + k0 + kc);
            As[(kc + 0) * SSTR + r] = tfr(av.x);
            As[(kc + 1) * SSTR + r] = tfr(av.y);
            As[(kc + 2) * SSTR + r] = tfr(av.z);
            As[(kc + 3) * SSTR + r] = tfr(av.w);
            int kb = q >> 5;
            int n4 = (q & 31) << 2;
            float4 bv = *(const float4*)(gB + (size_t)(k0 + kb) * N + n4);
            float4 bt = make_float4(tfr(bv.x), tfr(bv.y), tfr(bv.z), tfr(bv.w));
            *(float4*)(Bs + kb * SSTR + n4) = bt;
        }
        __syncthreads();

        #pragma unroll
        for (int kk = 0; kk < 4; ++kk) {
            const int kb = kk * 8;
            unsigned a[4][4], b[4][2];
            #pragma unroll
            for (int mt = 0; mt < 4; ++mt) {
                int Rm = warpM + mt * 16 + gr;
                a[mt][0] = fu(As[(kb + gc) * SSTR + Rm]);
                a[mt][1] = fu(As[(kb + gc) * SSTR + Rm + 8]);
                a[mt][2] = fu(As[(kb + 4 + gc) * SSTR + Rm]);
                a[mt][3] = fu(As[(kb + 4 + gc) * SSTR + Rm + 8]);
            }
            #pragma unroll
            for (int nt = 0; nt < 4; ++nt) {
                int Cn = warpN + nt * 8 + gr;
                b[nt][0] = fu(Bs[(kb + gc) * SSTR + Cn]);
                b[nt][1] = fu(Bs[(kb + 4 + gc) * SSTR + Cn]);
            }
            #pragma unroll
            for (int mt = 0; mt < 4; ++mt)
                #pragma unroll
                for (int nt = 0; nt < 4; ++nt)
                    mma_tf32(acc[mt][nt], a[mt], b[nt]);
        }
    }

    float* Cbase = C + (size_t)(cRow * 128 + warpM + gr) * N
                     + cCol * 128 + warpN + 2 * gc;
    #pragma unroll
    for (int mt = 0; mt < 4; ++mt)
        #pragma unroll
        for (int nt = 0; nt < 4; ++nt) {
            float* p = Cbase + (size_t)(mt * 16) * N + nt * 8;
            *(float2*)p                   = make_float2(acc[mt][nt][0], acc[mt][nt][1]);
            *(float2*)(p + (size_t)8 * N) = make_float2(acc[mt][nt][2], acc[mt][nt][3]);
        }
}

// ---------------- fused QKV projection --------------------------------------
__global__ void __launch_bounds__(256) gemm_qkv_kernel(const float* __restrict__ hs,
                                                       const float* __restrict__ wq,
                                                       const float* __restrict__ wk,
                                                       const float* __restrict__ wv)
{
    int z = blockIdx.z;
    if (z == 0) {
        gemm_tf32(hs, wq, g_Q, QDIM, HID, blockIdx.y, blockIdx.x);
    } else if (z == 1) {
        if (blockIdx.x >= KVDIM / 128) return;
        gemm_tf32(hs, wk, g_K, KVDIM, HID, blockIdx.y, blockIdx.x);
    } else {
        if (blockIdx.x >= KVDIM / 128) return;
        gemm_tf32(hs, wv, g_V, KVDIM, HID, blockIdx.y, blockIdx.x);
    }
}

// ---------------- output projection ------------------------------------------
__global__ void __launch_bounds__(256) gemm_out_kernel(const float* __restrict__ wo,
                                                       float* __restrict__ out)
{
    gemm_tf32(g_AO, wo, out, HID, QDIM, blockIdx.y, blockIdx.x);
}

// ---------------- RMSNorm + RoPE (in place on g_Q / g_K) --------------------
__global__ void __launch_bounds__(128) rmsnorm_rope_kernel(const float* __restrict__ cos_t,
                                                           const float* __restrict__ sin_t,
                                                           const float* __restrict__ qw,
                                                           const float* __restrict__ kw)
{
    const int s = blockIdx.x;
    const int h = blockIdx.y;
    const int d = threadIdx.x;

    float* base;
    const float* w;
    float scl;
    if (h < NH) { base = g_Q + (size_t)s * QDIM + h * HD;         w = qw; scl = SCALE; }
    else        { base = g_K + (size_t)s * KVDIM + (h - NH) * HD; w = kw; scl = 1.0f; }

    float x = base[d];
    float v = x * x;
    #pragma unroll
    for (int off = 16; off; off >>= 1) v += __shfl_xor_sync(0xffffffffu, v, off);
    __shared__ float wsum[4];
    if ((d & 31) == 0) wsum[d >> 5] = v;
    __syncthreads();
    float rinv = rsqrtf((wsum[0] + wsum[1] + wsum[2] + wsum[3]) * (1.0f / HD) + EPS);

    float xn = x * rinv * w[d];
    __shared__ float sh[HD];
    sh[d] = xn;
    __syncthreads();
    float rot = (d < HD / 2) ? -sh[d + HD / 2] : sh[d - HD / 2];
    float c  = cos_t[(size_t)s * HD + d];
    float sn = sin_t[(size_t)s * HD + d];
    base[d] = (xn * c + rot * sn) * scl;
}

// ---------------- flash attention (tf32 tensor cores, causal, GQA) ----------
// BQ = BK = 64. 8 warps. QK^T: warp (mw=w>>1, nw=w&1) -> rows mw*16, cols nw*32.
// P*V:  same mw rows, dims nw*64. Q frags in registers for the whole kernel.
#define FSTR  132   // K/V smem stride (132 % 32 == 4 -> conflict-free frags)
#define FPSTR 68    // P smem stride   (68 % 32 == 4)
#define FLASH_SMEM ((2 * 64 * FSTR + 64 * FPSTR + 128) * 4)

__global__ void __launch_bounds__(256, 1) flash_kernel()
{
    const int h  = blockIdx.y;
    const int g  = h >> 1;
    const int qb = blockIdx.x;
    const int q0 = qb * 64;
    const int tid  = threadIdx.x;
    const int lane = tid & 31;
    const int w    = tid >> 5;
    const int mw = w >> 1;
    const int nw = w & 1;
    const int gr = lane >> 2;
    const int gc = lane & 3;
    const int Rm = mw * 16 + gr;

    extern __shared__ float sm[];
    float* Ks = sm;                    // [64][FSTR]
    float* Vs = Ks + 64 * FSTR;        // [64][FSTR]
    float* Ps = Vs + 64 * FSTR;        // [64][FPSTR]
    float* Al = Ps + 64 * FPSTR;       // alpha[64]
    float* Li = Al + 64;               // l[64]

    // ---- stage Q through Ks, pull a-fragments into registers ----
    for (int t = tid; t < 64 * 32; t += 256) {
        int r = t >> 5, c4 = (t & 31) << 2;
        float4 v = *(const float4*)(g_Q + (size_t)(q0 + r) * QDIM + h * HD + c4);
        float* d = Ks + r * FSTR + c4;
        d[0] = tfr(v.x); d[1] = tfr(v.y); d[2] = tfr(v.z); d[3] = tfr(v.w);
    }
    __syncthreads();
    unsigned qa[16][4];
    #pragma unroll
    for (int ks = 0; ks < 16; ++ks) {
        int kb = ks * 8;
        qa[ks][0] = fu(Ks[Rm * FSTR + kb + gc]);
        qa[ks][1] = fu(Ks[(Rm + 8) * FSTR + kb + gc]);
        qa[ks][2] = fu(Ks[Rm * FSTR + kb + 4 + gc]);
        qa[ks][3] = fu(Ks[(Rm + 8) * FSTR + kb + 4 + gc]);
    }

    // softmax state: thread owns row srow (4 threads per row, redundant state)
    const int srow = tid >> 2;
    const int scol = (tid & 3) * 16;
    float mrow = -1e30f, lrow = 0.f;

    float O[8][4];
    #pragma unroll
    for (int nt = 0; nt < 8; ++nt)
        #pragma unroll
        for (int i = 0; i < 4; ++i) O[nt][i] = 0.f;

    for (int kt = 0; kt <= qb; ++kt) {
        const int k0 = kt * 64;
        __syncthreads();   // protect Ks/Vs/Ps from previous iteration (and qa loads)
        for (int t = tid; t < 64 * 32; t += 256) {
            int r = t >> 5, c4 = (t & 31) << 2;
            float4 kv = *(const float4*)(g_K + (size_t)(k0 + r) * KVDIM + g * HD + c4);
            float4 vv = *(const float4*)(g_V + (size_t)(k0 + r) * KVDIM + g * HD + c4);
            float* kd = Ks + r * FSTR + c4;
            kd[0] = tfr(kv.x); kd[1] = tfr(kv.y); kd[2] = tfr(kv.z); kd[3] = tfr(kv.w);
            float* vd = Vs + r * FSTR + c4;
            vd[0] = tfr(vv.x); vd[1] = tfr(vv.y); vd[2] = tfr(vv.z); vd[3] = tfr(vv.w);
        }
        __syncthreads();

        // ---- S = Q K^T ----
        float S[4][4];
        #pragma unroll
        for (int nt = 0; nt < 4; ++nt)
            #pragma unroll
            for (int i = 0; i < 4; ++i) S[nt][i] = 0.f;
        #pragma unroll
        for (int ks = 0; ks < 16; ++ks) {
            int kb = ks * 8;
            unsigned b[4][2];
            #pragma unroll
            for (int nt = 0; nt < 4; ++nt) {
                int Cn = nw * 32 + nt * 8 + gr;
                b[nt][0] = fu(Ks[Cn * FSTR + kb + gc]);
                b[nt][1] = fu(Ks[Cn * FSTR + kb + 4 + gc]);
            }
            #pragma unroll
            for (int nt = 0; nt < 4; ++nt)
                mma_tf32(S[nt], qa[ks], b[nt]);
        }
        // write S to Ps (+ diagonal causal mask; k0 == q0 on the diagonal tile)
        #pragma unroll
        for (int nt = 0; nt < 4; ++nt) {
            int Cn = nw * 32 + nt * 8 + 2 * gc;
            if (kt == qb) {
                if (Cn     > Rm)     S[nt][0] = -1e30f;
                if (Cn + 1 > Rm)     S[nt][1] = -1e30f;
                if (Cn     > Rm + 8) S[nt][2] = -1e30f;
                if (Cn + 1 > Rm + 8) S[nt][3] = -1e30f;
            }
            *(float2*)(Ps + Rm * FPSTR + Cn)       = make_float2(S[nt][0], S[nt][1]);
            *(float2*)(Ps + (Rm + 8) * FPSTR + Cn) = make_float2(S[nt][2], S[nt][3]);
        }
        __syncthreads();

        // ---- online softmax (SIMT over Ps) ----
        {
            float v[16];
            #pragma unroll
            for (int i = 0; i < 16; i += 4)
                *(float4*)(v + i) = *(const float4*)(Ps + srow * FPSTR + scol + i);
            float mx = v[0];
            #pragma unroll
            for (int i = 1; i < 16; ++i) mx = fmaxf(mx, v[i]);
            mx = fmaxf(mx, __shfl_xor_sync(0xffffffffu, mx, 1));
            mx = fmaxf(mx, __shfl_xor_sync(0xffffffffu, mx, 2));
            float mnew  = fmaxf(mrow, mx);
            float alpha = __expf(mrow - mnew);
            float s = 0.f;
            #pragma unroll
            for (int i = 0; i < 16; ++i) { v[i] = __expf(v[i] - mnew); s += v[i]; }
            s += __shfl_xor_sync(0xffffffffu, s, 1);
            s += __shfl_xor_sync(0xffffffffu, s, 2);
            lrow = lrow * alpha + s;
            mrow = mnew;
            #pragma unroll
            for (int i = 0; i < 16; ++i) v[i] = tfr(v[i]);
            #pragma unroll
            for (int i = 0; i < 16; i += 4)
                *(float4*)(Ps + srow * FPSTR + scol + i) = *(const float4*)(v + i);
            if ((tid & 3) == 0) Al[srow] = alpha;
        }
        __syncthreads();

        // ---- rescale O, then O += P V ----
        {
            float a0 = Al[Rm], a1 = Al[Rm + 8];
            #pragma unroll
            for (int nt = 0; nt < 8; ++nt) {
                O[nt][0] *= a0; O[nt][1] *= a0;
                O[nt][2] *= a1; O[nt][3] *= a1;
            }
            #pragma unroll
            for (int ks = 0; ks < 8; ++ks) {
                int kb = ks * 8;
                unsigned a[4];
                a[0] = fu(Ps[Rm * FPSTR + kb + gc]);
                a[1] = fu(Ps[(Rm + 8) * FPSTR + kb + gc]);
                a[2] = fu(Ps[Rm * FPSTR + kb + 4 + gc]);
                a[3] = fu(Ps[(Rm + 8) * FPSTR + kb + 4 + gc]);
                #pragma unroll
                for (int nt = 0; nt < 8; ++nt) {
                    int Dn = nw * 64 + nt * 8 + gr;
                    unsigned b[2];
                    b[0] = fu(Vs[(kb + gc) * FSTR + Dn]);
                    b[1] = fu(Vs[(kb + 4 + gc) * FSTR + Dn]);
                    mma_tf32(O[nt], a, b);
                }
            }
        }
    }

    if ((tid & 3) == 0) Li[srow] = lrow;
    __syncthreads();
    {
        float i0 = 1.f / Li[Rm], i1 = 1.f / Li[Rm + 8];
        #pragma unroll
        for (int nt = 0; nt < 8; ++nt) {
            int Dn = nw * 64 + nt * 8 + 2 * gc;
            float* p0 = g_AO + (size_t)(q0 + Rm) * QDIM + h * HD + Dn;
            *(float2*)p0 = make_float2(O[nt][0] * i0, O[nt][1] * i0);
            float* p1 = g_AO + (size_t)(q0 + Rm + 8) * QDIM + h * HD + Dn;
            *(float2*)p1 = make_float2(O[nt][2] * i1, O[nt][3] * i1);
        }
    }
}

// ---------------- launch ------------------------------------------------------
extern "C" void kernel_launch(void* const* d_in, const int* in_sizes, int n_in,
                              void* d_out, int out_size)
{
    const float* hs    = (const float*)d_in[0];
    const float* cos_t = (const float*)d_in[1];
    const float* sin_t = (const float*)d_in[2];
    // d_in[3] = attention_mask (causal tril; applied analytically)
    const float* wq = (const float*)d_in[4];
    const float* wk = (const float*)d_in[5];
    const float* wv = (const float*)d_in[6];
    const float* wo = (const float*)d_in[7];
    const float* qw = (const float*)d_in[8];
    const float* kw = (const float*)d_in[9];
    float* out = (float*)d_out;

    cudaFuncSetAttribute(flash_kernel,
                         cudaFuncAttributeMaxDynamicSharedMemorySize, FLASH_SMEM);

    gemm_qkv_kernel<<<dim3(QDIM / 128, S_LEN / 128, 3), 256>>>(hs, wq, wk, wv);
    rmsnorm_rope_kernel<<<dim3(S_LEN, NH + NKV), 128>>>(cos_t, sin_t, qw, kw);
    flash_kernel<<<dim3(S_LEN / 64, NH), 256, FLASH_SMEM>>>();
    gemm_out_kernel<<<dim3(HID / 128, S_LEN / 128), 256>>>(wo, out);
}

// round 13
// speedup vs baseline: 2.7427x; 1.0535x over previous
#include <cuda_runtime.h>
#include <cuda_bf16.h>

#define S_LEN 2048
#define HID   2048
#define NH    16
#define NKV   8
#define HD    128
#define QDIM  (NH * HD)    // 2048
#define KVDIM (NKV * HD)   // 1024
#define SCALE 0.08838834764831845f
#define EPS   1e-6f

// ---------------- scratch (device globals; no allocation allowed) ----------
__device__ float g_Q[S_LEN * QDIM];    // 16 MB
__device__ float g_K[S_LEN * KVDIM];   //  8 MB
__device__ float g_V[S_LEN * KVDIM];   //  8 MB
__device__ float g_AO[S_LEN * QDIM];   // 16 MB

// ---------------- tf32 helpers ----------------------------------------------
__device__ __forceinline__ unsigned f2tf(float x) {
    unsigned u;
    asm("cvt.rna.tf32.f32 %0, %1;" : "=r"(u) : "f"(x));
    return u;
}
__device__ __forceinline__ float tfr(float x) { return __uint_as_float(f2tf(x)); }
__device__ __forceinline__ unsigned fu(float x) { return __float_as_uint(x); }

__device__ __forceinline__ void mma_tf32(float c[4], const unsigned a[4], const unsigned b[2]) {
    asm volatile(
        "mma.sync.aligned.m16n8k8.row.col.f32.tf32.tf32.f32 "
        "{%0,%1,%2,%3}, {%4,%5,%6,%7}, {%8,%9}, {%0,%1,%2,%3};"
        : "+f"(c[0]), "+f"(c[1]), "+f"(c[2]), "+f"(c[3])
        : "r"(a[0]), "r"(a[1]), "r"(a[2]), "r"(a[3]), "r"(b[0]), "r"(b[1]));
}

// ---------------- tf32 tensor-core GEMM: 128x128 block tile -----------------
// 256 threads = 8 warps in 2(M) x 4(N); warp tile 64x32; mma m16n8k8 tf32.
// Register-prefetch double buffering: LDG for tile it+1 issued before compute
// of tile it, hiding global-load latency behind the 64 mma ops.
#define KSTEP 32
#define SSTR  136

__device__ __forceinline__ void gemm_tf32(const float* __restrict__ A,
                                          const float* __restrict__ B,
                                          float* __restrict__ C,
                                          int N, int K, int cRow, int cCol)
{
    __shared__ float As[KSTEP * SSTR];   // [k][m]
    __shared__ float Bs[KSTEP * SSTR];   // [k][n]

    const int tid  = threadIdx.x;
    const int lane = tid & 31;
    const int w    = tid >> 5;
    const int warpM = (w >> 2) * 64;
    const int warpN = (w & 3) * 32;
    const int gr = lane >> 2;
    const int gc = lane & 3;

    const float* gA = A + (size_t)(cRow * 128) * K;
    const float* gB = B + (size_t)cCol * 128;

    // per-thread load coordinates (i adds 32 rows for A / 8 rows for B)
    const int arow = tid >> 3;            // 0..31
    const int acol = (tid & 7) << 2;      // 0..28
    const int brow = tid >> 5;            // 0..7
    const int bcol = (tid & 31) << 2;     // 0..124

    float4 pa[4], pb[4];
    auto ldg_tiles = [&](int k0) {
        #pragma unroll
        for (int i = 0; i < 4; ++i) {
            pa[i] = *(const float4*)(gA + (size_t)(arow + 32 * i) * K + k0 + acol);
            pb[i] = *(const float4*)(gB + (size_t)(k0 + brow + 8 * i) * N + bcol);
        }
    };

    float acc[4][4][4];
    #pragma unroll
    for (int mt = 0; mt < 4; ++mt)
        #pragma unroll
        for (int nt = 0; nt < 4; ++nt)
            #pragma unroll
            for (int i = 0; i < 4; ++i) acc[mt][nt][i] = 0.f;

    const int NK = K / KSTEP;
    ldg_tiles(0);

    for (int it = 0; it < NK; ++it) {
        __syncthreads();   // previous compute done reading smem
        #pragma unroll
        for (int i = 0; i < 4; ++i) {
            int r = arow + 32 * i;
            As[(acol + 0) * SSTR + r] = tfr(pa[i].x);
            As[(acol + 1) * SSTR + r] = tfr(pa[i].y);
            As[(acol + 2) * SSTR + r] = tfr(pa[i].z);
            As[(acol + 3) * SSTR + r] = tfr(pa[i].w);
            int kb = brow + 8 * i;
            float4 bt = make_float4(tfr(pb[i].x), tfr(pb[i].y), tfr(pb[i].z), tfr(pb[i].w));
            *(float4*)(Bs + kb * SSTR + bcol) = bt;
        }
        __syncthreads();
        if (it + 1 < NK) ldg_tiles((it + 1) * KSTEP);   // overlap with compute below

        #pragma unroll
        for (int kk = 0; kk < 4; ++kk) {
            const int kb = kk * 8;
            unsigned a[4][4], b[4][2];
            #pragma unroll
            for (int mt = 0; mt < 4; ++mt) {
                int Rm = warpM + mt * 16 + gr;
                a[mt][0] = fu(As[(kb + gc) * SSTR + Rm]);
                a[mt][1] = fu(As[(kb + gc) * SSTR + Rm + 8]);
                a[mt][2] = fu(As[(kb + 4 + gc) * SSTR + Rm]);
                a[mt][3] = fu(As[(kb + 4 + gc) * SSTR + Rm + 8]);
            }
            #pragma unroll
            for (int nt = 0; nt < 4; ++nt) {
                int Cn = warpN + nt * 8 + gr;
                b[nt][0] = fu(Bs[(kb + gc) * SSTR + Cn]);
                b[nt][1] = fu(Bs[(kb + 4 + gc) * SSTR + Cn]);
            }
            #pragma unroll
            for (int mt = 0; mt < 4; ++mt)
                #pragma unroll
                for (int nt = 0; nt < 4; ++nt)
                    mma_tf32(acc[mt][nt], a[mt], b[nt]);
        }
    }

    float* Cbase = C + (size_t)(cRow * 128 + warpM + gr) * N
                     + cCol * 128 + warpN + 2 * gc;
    #pragma unroll
    for (int mt = 0; mt < 4; ++mt)
        #pragma unroll
        for (int nt = 0; nt < 4; ++nt) {
            float* p = Cbase + (size_t)(mt * 16) * N + nt * 8;
            *(float2*)p                   = make_float2(acc[mt][nt][0], acc[mt][nt][1]);
            *(float2*)(p + (size_t)8 * N) = make_float2(acc[mt][nt][2], acc[mt][nt][3]);
        }
}

// ---------------- fused QKV projection --------------------------------------
__global__ void __launch_bounds__(256) gemm_qkv_kernel(const float* __restrict__ hs,
                                                       const float* __restrict__ wq,
                                                       const float* __restrict__ wk,
                                                       const float* __restrict__ wv)
{
    int z = blockIdx.z;
    if (z == 0) {
        gemm_tf32(hs, wq, g_Q, QDIM, HID, blockIdx.y, blockIdx.x);
    } else if (z == 1) {
        if (blockIdx.x >= KVDIM / 128) return;
        gemm_tf32(hs, wk, g_K, KVDIM, HID, blockIdx.y, blockIdx.x);
    } else {
        if (blockIdx.x >= KVDIM / 128) return;
        gemm_tf32(hs, wv, g_V, KVDIM, HID, blockIdx.y, blockIdx.x);
    }
}

// ---------------- output projection ------------------------------------------
__global__ void __launch_bounds__(256) gemm_out_kernel(const float* __restrict__ wo,
                                                       float* __restrict__ out)
{
    gemm_tf32(g_AO, wo, out, HID, QDIM, blockIdx.y, blockIdx.x);
}

// ---------------- RMSNorm + RoPE (in place on g_Q / g_K) --------------------
__global__ void __launch_bounds__(128) rmsnorm_rope_kernel(const float* __restrict__ cos_t,
                                                           const float* __restrict__ sin_t,
                                                           const float* __restrict__ qw,
                                                           const float* __restrict__ kw)
{
    const int s = blockIdx.x;
    const int h = blockIdx.y;
    const int d = threadIdx.x;

    float* base;
    const float* w;
    float scl;
    if (h < NH) { base = g_Q + (size_t)s * QDIM + h * HD;         w = qw; scl = SCALE; }
    else        { base = g_K + (size_t)s * KVDIM + (h - NH) * HD; w = kw; scl = 1.0f; }

    float x = base[d];
    float v = x * x;
    #pragma unroll
    for (int off = 16; off; off >>= 1) v += __shfl_xor_sync(0xffffffffu, v, off);
    __shared__ float wsum[4];
    if ((d & 31) == 0) wsum[d >> 5] = v;
    __syncthreads();
    float rinv = rsqrtf((wsum[0] + wsum[1] + wsum[2] + wsum[3]) * (1.0f / HD) + EPS);

    float xn = x * rinv * w[d];
    __shared__ float sh[HD];
    sh[d] = xn;
    __syncthreads();
    float rot = (d < HD / 2) ? -sh[d + HD / 2] : sh[d - HD / 2];
    float c  = cos_t[(size_t)s * HD + d];
    float sn = sin_t[(size_t)s * HD + d];
    base[d] = (xn * c + rot * sn) * scl;
}

// ---------------- flash attention (tf32 tensor cores, causal, GQA) ----------
// BQ = BK = 64. 8 warps. QK^T: warp (mw=w>>1, nw=w&1) -> rows mw*16, cols nw*32.
// P*V:  same mw rows, dims nw*64. Q frags in registers for the whole kernel.
#define FSTR  132   // K/V smem stride (132 % 32 == 4 -> conflict-free frags)
#define FPSTR 68    // P smem stride   (68 % 32 == 4)
#define FLASH_SMEM ((2 * 64 * FSTR + 64 * FPSTR + 128) * 4)

__global__ void __launch_bounds__(256, 1) flash_kernel()
{
    const int h  = blockIdx.y;
    const int g  = h >> 1;
    const int qb = blockIdx.x;
    const int q0 = qb * 64;
    const int tid  = threadIdx.x;
    const int lane = tid & 31;
    const int w    = tid >> 5;
    const int mw = w >> 1;
    const int nw = w & 1;
    const int gr = lane >> 2;
    const int gc = lane & 3;
    const int Rm = mw * 16 + gr;

    extern __shared__ float sm[];
    float* Ks = sm;                    // [64][FSTR]
    float* Vs = Ks + 64 * FSTR;        // [64][FSTR]
    float* Ps = Vs + 64 * FSTR;        // [64][FPSTR]
    float* Al = Ps + 64 * FPSTR;       // alpha[64]
    float* Li = Al + 64;               // l[64]

    // ---- stage Q through Ks, pull a-fragments into registers ----
    for (int t = tid; t < 64 * 32; t += 256) {
        int r = t >> 5, c4 = (t & 31) << 2;
        float4 v = *(const float4*)(g_Q + (size_t)(q0 + r) * QDIM + h * HD + c4);
        float* d = Ks + r * FSTR + c4;
        d[0] = tfr(v.x); d[1] = tfr(v.y); d[2] = tfr(v.z); d[3] = tfr(v.w);
    }
    __syncthreads();
    unsigned qa[16][4];
    #pragma unroll
    for (int ks = 0; ks < 16; ++ks) {
        int kb = ks * 8;
        qa[ks][0] = fu(Ks[Rm * FSTR + kb + gc]);
        qa[ks][1] = fu(Ks[(Rm + 8) * FSTR + kb + gc]);
        qa[ks][2] = fu(Ks[Rm * FSTR + kb + 4 + gc]);
        qa[ks][3] = fu(Ks[(Rm + 8) * FSTR + kb + 4 + gc]);
    }

    // softmax state: thread owns row srow (4 threads per row, redundant state)
    const int srow = tid >> 2;
    const int scol = (tid & 3) * 16;
    float mrow = -1e30f, lrow = 0.f;

    float O[8][4];
    #pragma unroll
    for (int nt = 0; nt < 8; ++nt)
        #pragma unroll
        for (int i = 0; i < 4; ++i) O[nt][i] = 0.f;

    for (int kt = 0; kt <= qb; ++kt) {
        const int k0 = kt * 64;
        __syncthreads();   // protect Ks/Vs/Ps from previous iteration (and qa loads)
        for (int t = tid; t < 64 * 32; t += 256) {
            int r = t >> 5, c4 = (t & 31) << 2;
            float4 kv = *(const float4*)(g_K + (size_t)(k0 + r) * KVDIM + g * HD + c4);
            float4 vv = *(const float4*)(g_V + (size_t)(k0 + r) * KVDIM + g * HD + c4);
            float* kd = Ks + r * FSTR + c4;
            kd[0] = tfr(kv.x); kd[1] = tfr(kv.y); kd[2] = tfr(kv.z); kd[3] = tfr(kv.w);
            float* vd = Vs + r * FSTR + c4;
            vd[0] = tfr(vv.x); vd[1] = tfr(vv.y); vd[2] = tfr(vv.z); vd[3] = tfr(vv.w);
        }
        __syncthreads();

        // ---- S = Q K^T ----
        float S[4][4];
        #pragma unroll
        for (int nt = 0; nt < 4; ++nt)
            #pragma unroll
            for (int i = 0; i < 4; ++i) S[nt][i] = 0.f;
        #pragma unroll
        for (int ks = 0; ks < 16; ++ks) {
            int kb = ks * 8;
            unsigned b[4][2];
            #pragma unroll
            for (int nt = 0; nt < 4; ++nt) {
                int Cn = nw * 32 + nt * 8 + gr;
                b[nt][0] = fu(Ks[Cn * FSTR + kb + gc]);
                b[nt][1] = fu(Ks[Cn * FSTR + kb + 4 + gc]);
            }
            #pragma unroll
            for (int nt = 0; nt < 4; ++nt)
                mma_tf32(S[nt], qa[ks], b[nt]);
        }
        // write S to Ps (+ diagonal causal mask; k0 == q0 on the diagonal tile)
        #pragma unroll
        for (int nt = 0; nt < 4; ++nt) {
            int Cn = nw * 32 + nt * 8 + 2 * gc;
            if (kt == qb) {
                if (Cn     > Rm)     S[nt][0] = -1e30f;
                if (Cn + 1 > Rm)     S[nt][1] = -1e30f;
                if (Cn     > Rm + 8) S[nt][2] = -1e30f;
                if (Cn + 1 > Rm + 8) S[nt][3] = -1e30f;
            }
            *(float2*)(Ps + Rm * FPSTR + Cn)       = make_float2(S[nt][0], S[nt][1]);
            *(float2*)(Ps + (Rm + 8) * FPSTR + Cn) = make_float2(S[nt][2], S[nt][3]);
        }
        __syncthreads();

        // ---- online softmax (SIMT over Ps) ----
        {
            float v[16];
            #pragma unroll
            for (int i = 0; i < 16; i += 4)
                *(float4*)(v + i) = *(const float4*)(Ps + srow * FPSTR + scol + i);
            float mx = v[0];
            #pragma unroll
            for (int i = 1; i < 16; ++i) mx = fmaxf(mx, v[i]);
            mx = fmaxf(mx, __shfl_xor_sync(0xffffffffu, mx, 1));
            mx = fmaxf(mx, __shfl_xor_sync(0xffffffffu, mx, 2));
            float mnew  = fmaxf(mrow, mx);
            float alpha = __expf(mrow - mnew);
            float s = 0.f;
            #pragma unroll
            for (int i = 0; i < 16; ++i) { v[i] = __expf(v[i] - mnew); s += v[i]; }
            s += __shfl_xor_sync(0xffffffffu, s, 1);
            s += __shfl_xor_sync(0xffffffffu, s, 2);
            lrow = lrow * alpha + s;
            mrow = mnew;
            #pragma unroll
            for (int i = 0; i < 16; ++i) v[i] = tfr(v[i]);
            #pragma unroll
            for (int i = 0; i < 16; i += 4)
                *(float4*)(Ps + srow * FPSTR + scol + i) = *(const float4*)(v + i);
            if ((tid & 3) == 0) Al[srow] = alpha;
        }
        __syncthreads();

        // ---- rescale O, then O += P V ----
        {
            float a0 = Al[Rm], a1 = Al[Rm + 8];
            #pragma unroll
            for (int nt = 0; nt < 8; ++nt) {
                O[nt][0] *= a0; O[nt][1] *= a0;
                O[nt][2] *= a1; O[nt][3] *= a1;
            }
            #pragma unroll
            for (int ks = 0; ks < 8; ++ks) {
                int kb = ks * 8;
                unsigned a[4];
                a[0] = fu(Ps[Rm * FPSTR + kb + gc]);
                a[1] = fu(Ps[(Rm + 8) * FPSTR + kb + gc]);
                a[2] = fu(Ps[Rm * FPSTR + kb + 4 + gc]);
                a[3] = fu(Ps[(Rm + 8) * FPSTR + kb + 4 + gc]);
                #pragma unroll
                for (int nt = 0; nt < 8; ++nt) {
                    int Dn = nw * 64 + nt * 8 + gr;
                    unsigned b[2];
                    b[0] = fu(Vs[(kb + gc) * FSTR + Dn]);
                    b[1] = fu(Vs[(kb + 4 + gc) * FSTR + Dn]);
                    mma_tf32(O[nt], a, b);
                }
            }
        }
    }

    if ((tid & 3) == 0) Li[srow] = lrow;
    __syncthreads();
    {
        float i0 = 1.f / Li[Rm], i1 = 1.f / Li[Rm + 8];
        #pragma unroll
        for (int nt = 0; nt < 8; ++nt) {
            int Dn = nw * 64 + nt * 8 + 2 * gc;
            float* p0 = g_AO + (size_t)(q0 + Rm) * QDIM + h * HD + Dn;
            *(float2*)p0 = make_float2(O[nt][0] * i0, O[nt][1] * i0);
            float* p1 = g_AO + (size_t)(q0 + Rm + 8) * QDIM + h * HD + Dn;
            *(float2*)p1 = make_float2(O[nt][2] * i1, O[nt][3] * i1);
        }
    }
}

// ---------------- launch ------------------------------------------------------
extern "C" void kernel_launch(void* const* d_in, const int* in_sizes, int n_in,
                              void* d_out, int out_size)
{
    const float* hs    = (const float*)d_in[0];
    const float* cos_t = (const float*)d_in[1];
    const float* sin_t = (const float*)d_in[2];
    // d_in[3] = attention_mask (causal tril; applied analytically)
    const float* wq = (const float*)d_in[4];
    const float* wk = (const float*)d_in[5];
    const float* wv = (const float*)d_in[6];
    const float* wo = (const float*)d_in[7];
    const float* qw = (const float*)d_in[8];
    const float* kw = (const float*)d_in[9];
    float* out = (float*)d_out;

    cudaFuncSetAttribute(flash_kernel,
                         cudaFuncAttributeMaxDynamicSharedMemorySize, FLASH_SMEM);

    gemm_qkv_kernel<<<dim3(QDIM / 128, S_LEN / 128, 3), 256>>>(hs, wq, wk, wv);
    rmsnorm_rope_kernel<<<dim3(S_LEN, NH + NKV), 128>>>(cos_t, sin_t, qw, kw);
    flash_kernel<<<dim3(S_LEN / 64, NH), 256, FLASH_SMEM>>>();
    gemm_out_kernel<<<dim3(HID / 128, S_LEN / 128), 256>>>(wo, out);
}

// round 16
// speedup vs baseline: 2.9695x; 1.0827x over previous
#include <cuda_runtime.h>
#include <cuda_bf16.h>

#define S_LEN 2048
#define HID   2048
#define NH    16
#define NKV   8
#define HD    128
#define QDIM  (NH * HD)    // 2048
#define KVDIM (NKV * HD)   // 1024
#define SCALE 0.08838834764831845f
#define EPS   1e-6f

// ---------------- scratch (device globals; no allocation allowed) ----------
__device__ float g_Q[S_LEN * QDIM];    // 16 MB
__device__ float g_K[S_LEN * KVDIM];   //  8 MB
__device__ float g_V[S_LEN * KVDIM];   //  8 MB
__device__ float g_AO[S_LEN * QDIM];   // 16 MB

// ---------------- tf32 helpers ----------------------------------------------
__device__ __forceinline__ unsigned f2tf(float x) {
    unsigned u;
    asm("cvt.rna.tf32.f32 %0, %1;" : "=r"(u) : "f"(x));
    return u;
}
__device__ __forceinline__ float tfr(float x) { return __uint_as_float(f2tf(x)); }
__device__ __forceinline__ unsigned fu(float x) { return __float_as_uint(x); }

__device__ __forceinline__ void mma_tf32(float c[4], const unsigned a[4], const unsigned b[2]) {
    asm volatile(
        "mma.sync.aligned.m16n8k8.row.col.f32.tf32.tf32.f32 "
        "{%0,%1,%2,%3}, {%4,%5,%6,%7}, {%8,%9}, {%0,%1,%2,%3};"
        : "+f"(c[0]), "+f"(c[1]), "+f"(c[2]), "+f"(c[3])
        : "r"(a[0]), "r"(a[1]), "r"(a[2]), "r"(a[3]), "r"(b[0]), "r"(b[1]));
}

// ---------------- tf32 GEMM: 128x128 tile, KSTEP=16, 2-stage double buffer --
// A smem [m][k] stride 20 (frag banks 4*gr+gc, store float4 direct).
// B smem [k][n] stride 136 (frag banks 8*gc+gr, store float4 direct).
#define ASTR 20
#define BSTR 136

__device__ __forceinline__ void gemm_tf32(const float* __restrict__ A,
                                          const float* __restrict__ B,
                                          float* __restrict__ C,
                                          int N, int K, int cRow, int cCol)
{
    __shared__ float As[2][128 * ASTR];
    __shared__ float Bs[2][16 * BSTR];

    const int tid  = threadIdx.x;
    const int lane = tid & 31;
    const int w    = tid >> 5;
    const int warpM = (w >> 2) * 64;
    const int warpN = (w & 3) * 32;
    const int gr = lane >> 2;
    const int gc = lane & 3;

    const float* gA = A + (size_t)(cRow * 128) * K;
    const float* gB = B + (size_t)cCol * 128;

    const int arow = tid >> 2;            // 0..63  (+64 second half)
    const int acol = (tid & 3) << 2;      // 0,4,8,12
    const int brow = tid >> 5;            // 0..7   (+8 second half)
    const int bcol = (tid & 31) << 2;     // 0..124

    float4 pa[2], pb[2];
    auto ldg = [&](int k0) {
        pa[0] = *(const float4*)(gA + (size_t)arow * K + k0 + acol);
        pa[1] = *(const float4*)(gA + (size_t)(arow + 64) * K + k0 + acol);
        pb[0] = *(const float4*)(gB + (size_t)(k0 + brow) * N + bcol);
        pb[1] = *(const float4*)(gB + (size_t)(k0 + brow + 8) * N + bcol);
    };
    auto sts = [&](int buf) {
        #pragma unroll
        for (int i = 0; i < 2; ++i) {
            float4 at = make_float4(tfr(pa[i].x), tfr(pa[i].y), tfr(pa[i].z), tfr(pa[i].w));
            *(float4*)(&As[buf][(arow + 64 * i) * ASTR + acol]) = at;
            float4 bt = make_float4(tfr(pb[i].x), tfr(pb[i].y), tfr(pb[i].z), tfr(pb[i].w));
            *(float4*)(&Bs[buf][(brow + 8 * i) * BSTR + bcol]) = bt;
        }
    };

    float acc[4][4][4];
    #pragma unroll
    for (int mt = 0; mt < 4; ++mt)
        #pragma unroll
        for (int nt = 0; nt < 4; ++nt)
            #pragma unroll
            for (int i = 0; i < 4; ++i) acc[mt][nt][i] = 0.f;

    const int NK = K / 16;
    ldg(0);
    sts(0);
    __syncthreads();

    for (int it = 0; it < NK; ++it) {
        if (it + 1 < NK) ldg((it + 1) * 16);
        const float* cA = As[it & 1];
        const float* cB = Bs[it & 1];
        #pragma unroll
        for (int kk = 0; kk < 2; ++kk) {
            const int kb = kk * 8;
            unsigned a[4][4], b[4][2];
            #pragma unroll
            for (int mt = 0; mt < 4; ++mt) {
                int Rm = warpM + mt * 16 + gr;
                a[mt][0] = fu(cA[Rm * ASTR + kb + gc]);
                a[mt][1] = fu(cA[(Rm + 8) * ASTR + kb + gc]);
                a[mt][2] = fu(cA[Rm * ASTR + kb + 4 + gc]);
                a[mt][3] = fu(cA[(Rm + 8) * ASTR + kb + 4 + gc]);
            }
            #pragma unroll
            for (int nt = 0; nt < 4; ++nt) {
                int Cn = warpN + nt * 8 + gr;
                b[nt][0] = fu(cB[(kb + gc) * BSTR + Cn]);
                b[nt][1] = fu(cB[(kb + 4 + gc) * BSTR + Cn]);
            }
            #pragma unroll
            for (int mt = 0; mt < 4; ++mt)
                #pragma unroll
                for (int nt = 0; nt < 4; ++nt)
                    mma_tf32(acc[mt][nt], a[mt], b[nt]);
        }
        if (it + 1 < NK) sts((it + 1) & 1);
        __syncthreads();
    }

    float* Cbase = C + (size_t)(cRow * 128 + warpM + gr) * N
                     + cCol * 128 + warpN + 2 * gc;
    #pragma unroll
    for (int mt = 0; mt < 4; ++mt)
        #pragma unroll
        for (int nt = 0; nt < 4; ++nt) {
            float* p = Cbase + (size_t)(mt * 16) * N + nt * 8;
            *(float2*)p                   = make_float2(acc[mt][nt][0], acc[mt][nt][1]);
            *(float2*)(p + (size_t)8 * N) = make_float2(acc[mt][nt][2], acc[mt][nt][3]);
        }
}

// ---------------- fused QKV projection (flattened grid, no dead CTAs) -------
__global__ void __launch_bounds__(256, 2) gemm_qkv_kernel(const float* __restrict__ hs,
                                                          const float* __restrict__ wq,
                                                          const float* __restrict__ wk,
                                                          const float* __restrict__ wv)
{
    int idx = blockIdx.x;
    if (idx < 256) {
        gemm_tf32(hs, wq, g_Q, QDIM, HID, idx >> 4, idx & 15);
    } else if (idx < 384) {
        int t = idx - 256;
        gemm_tf32(hs, wk, g_K, KVDIM, HID, t >> 3, t & 7);
    } else {
        int t = idx - 384;
        gemm_tf32(hs, wv, g_V, KVDIM, HID, t >> 3, t & 7);
    }
}

// ---------------- output projection ------------------------------------------
__global__ void __launch_bounds__(256, 2) gemm_out_kernel(const float* __restrict__ wo,
                                                          float* __restrict__ out)
{
    gemm_tf32(g_AO, wo, out, HID, QDIM, blockIdx.x >> 4, blockIdx.x & 15);
}

// ---------------- RMSNorm + RoPE (in place on g_Q / g_K) --------------------
__global__ void __launch_bounds__(128) rmsnorm_rope_kernel(const float* __restrict__ cos_t,
                                                           const float* __restrict__ sin_t,
                                                           const float* __restrict__ qw,
                                                           const float* __restrict__ kw)
{
    const int s = blockIdx.x;
    const int h = blockIdx.y;
    const int d = threadIdx.x;

    float* base;
    const float* w;
    float scl;
    if (h < NH) { base = g_Q + (size_t)s * QDIM + h * HD;         w = qw; scl = SCALE; }
    else        { base = g_K + (size_t)s * KVDIM + (h - NH) * HD; w = kw; scl = 1.0f; }

    float x = base[d];
    float v = x * x;
    #pragma unroll
    for (int off = 16; off; off >>= 1) v += __shfl_xor_sync(0xffffffffu, v, off);
    __shared__ float wsum[4];
    if ((d & 31) == 0) wsum[d >> 5] = v;
    __syncthreads();
    float rinv = rsqrtf((wsum[0] + wsum[1] + wsum[2] + wsum[3]) * (1.0f / HD) + EPS);

    float xn = x * rinv * w[d];
    __shared__ float sh[HD];
    sh[d] = xn;
    __syncthreads();
    float rot = (d < HD / 2) ? -sh[d + HD / 2] : sh[d - HD / 2];
    float c  = cos_t[(size_t)s * HD + d];
    float sn = sin_t[(size_t)s * HD + d];
    base[d] = (xn * c + rot * sn) * scl;
}

// ---------------- flash attention: BQ=BK=32, 128 threads, 4 CTAs/SM ---------
// K and V share one [32][132] buffer: K phase = [n][hd], V phase = [k][hd].
// Qs[m][k] str 132 (persistent), Ps[m][k] str 36. All frag patterns bank
// conflict-free: stride%32==4 -> bank 4*gr+gc / 4*gc+..., verified per access.
#define QSTR 132
#define KVSTR 132
#define PSTR 36

__global__ void __launch_bounds__(128, 4) flash_kernel()
{
    __shared__ float Qs[32 * QSTR];     // 16.9 KB
    __shared__ float KVs[32 * KVSTR];   // 16.9 KB (K, then V)
    __shared__ float Ps[32 * PSTR];     //  4.6 KB
    __shared__ float Al[32];
    __shared__ float Li[32];

    const int h  = blockIdx.y;
    const int g  = h >> 1;
    const int qb = gridDim.x - 1 - blockIdx.x;   // big q-blocks first
    const int q0 = qb * 32;
    const int tid  = threadIdx.x;
    const int lane = tid & 31;
    const int w    = tid >> 5;
    const int mw = w >> 1;
    const int nw = w & 1;
    const int gr = lane >> 2;
    const int gc = lane & 3;
    const int Rm = mw * 16 + gr;       // rows: mw*16+gr, +8

    // ---- load Q tile [32 m][128 k] ----
    for (int t = tid; t < 32 * 32; t += 128) {
        int r = t >> 5, c4 = (t & 31) << 2;
        float4 v = *(const float4*)(g_Q + (size_t)(q0 + r) * QDIM + h * HD + c4);
        float* d = Qs + r * QSTR + c4;
        d[0] = tfr(v.x); d[1] = tfr(v.y); d[2] = tfr(v.z); d[3] = tfr(v.w);
    }

    const int srow = tid >> 2;         // 0..31
    const int scol = (tid & 3) * 8;    // 0,8,16,24
    float mrow = -1e30f, lrow = 0.f;

    float O[8][4];
    #pragma unroll
    for (int nt = 0; nt < 8; ++nt)
        #pragma unroll
        for (int i = 0; i < 4; ++i) O[nt][i] = 0.f;

    for (int kt = 0; kt <= qb; ++kt) {
        const int k0 = kt * 32;

        // ---- phase 1: load K tile [32 n][128 hd] into KVs ----
        __syncthreads();   // prior PV done reading KVs/Ps (covers Q staging on kt==0)
        for (int t = tid; t < 32 * 32; t += 128) {
            int r = t >> 5, c4 = (t & 31) << 2;
            float4 kv = *(const float4*)(g_K + (size_t)(k0 + r) * KVDIM + g * HD + c4);
            float* kd = KVs + r * KVSTR + c4;
            kd[0] = tfr(kv.x); kd[1] = tfr(kv.y); kd[2] = tfr(kv.z); kd[3] = tfr(kv.w);
        }
        __syncthreads();

        // ---- phase 2: S = Q K^T (contract over HD=128) ----
        float S[2][4];
        #pragma unroll
        for (int nt = 0; nt < 2; ++nt)
            #pragma unroll
            for (int i = 0; i < 4; ++i) S[nt][i] = 0.f;
        #pragma unroll
        for (int ks = 0; ks < 16; ++ks) {
            int kb = ks * 8;
            unsigned a[4], b[2][2];
            a[0] = fu(Qs[Rm * QSTR + kb + gc]);
            a[1] = fu(Qs[(Rm + 8) * QSTR + kb + gc]);
            a[2] = fu(Qs[Rm * QSTR + kb + 4 + gc]);
            a[3] = fu(Qs[(Rm + 8) * QSTR + kb + 4 + gc]);
            #pragma unroll
            for (int nt = 0; nt < 2; ++nt) {
                int Cn = nw * 16 + nt * 8 + gr;
                b[nt][0] = fu(KVs[Cn * KVSTR + kb + gc]);
                b[nt][1] = fu(KVs[Cn * KVSTR + kb + 4 + gc]);
            }
            #pragma unroll
            for (int nt = 0; nt < 2; ++nt)
                mma_tf32(S[nt], a, b[nt]);
        }
        // write S to Ps (+ causal mask on the diagonal tile, k0 == q0)
        #pragma unroll
        for (int nt = 0; nt < 2; ++nt) {
            int Cn = nw * 16 + nt * 8 + 2 * gc;
            if (kt == qb) {
                if (Cn     > Rm)     S[nt][0] = -1e30f;
                if (Cn + 1 > Rm)     S[nt][1] = -1e30f;
                if (Cn     > Rm + 8) S[nt][2] = -1e30f;
                if (Cn + 1 > Rm + 8) S[nt][3] = -1e30f;
            }
            *(float2*)(Ps + Rm * PSTR + Cn)       = make_float2(S[nt][0], S[nt][1]);
            *(float2*)(Ps + (Rm + 8) * PSTR + Cn) = make_float2(S[nt][2], S[nt][3]);
        }
        __syncthreads();   // K reads done + Ps(S) visible

        // ---- phase 3: load V tile [32 k][128 n] into KVs  +  softmax on Ps --
        for (int t = tid; t < 32 * 32; t += 128) {
            int r = t >> 5, c4 = (t & 31) << 2;
            float4 vv = *(const float4*)(g_V + (size_t)(k0 + r) * KVDIM + g * HD + c4);
            float* vd = KVs + r * KVSTR + c4;
            vd[0] = tfr(vv.x); vd[1] = tfr(vv.y); vd[2] = tfr(vv.z); vd[3] = tfr(vv.w);
        }
        {
            float v[8];
            *(float4*)(v)     = *(const float4*)(Ps + srow * PSTR + scol);
            *(float4*)(v + 4) = *(const float4*)(Ps + srow * PSTR + scol + 4);
            float mx = v[0];
            #pragma unroll
            for (int i = 1; i < 8; ++i) mx = fmaxf(mx, v[i]);
            mx = fmaxf(mx, __shfl_xor_sync(0xffffffffu, mx, 1));
            mx = fmaxf(mx, __shfl_xor_sync(0xffffffffu, mx, 2));
            float mnew  = fmaxf(mrow, mx);
            float alpha = __expf(mrow - mnew);
            float s = 0.f;
            #pragma unroll
            for (int i = 0; i < 8; ++i) { v[i] = __expf(v[i] - mnew); s += v[i]; }
            s += __shfl_xor_sync(0xffffffffu, s, 1);
            s += __shfl_xor_sync(0xffffffffu, s, 2);
            lrow = lrow * alpha + s;
            mrow = mnew;
            #pragma unroll
            for (int i = 0; i < 8; ++i) v[i] = tfr(v[i]);
            *(float4*)(Ps + srow * PSTR + scol)     = *(const float4*)(v);
            *(float4*)(Ps + srow * PSTR + scol + 4) = *(const float4*)(v + 4);
            if ((tid & 3) == 0) Al[srow] = alpha;
        }
        __syncthreads();   // V stored + Ps(exp)/Al visible

        // ---- phase 4: rescale O, then O += P V ----
        {
            float a0 = Al[Rm], a1 = Al[Rm + 8];
            #pragma unroll
            for (int nt = 0; nt < 8; ++nt) {
                O[nt][0] *= a0; O[nt][1] *= a0;
                O[nt][2] *= a1; O[nt][3] *= a1;
            }
            #pragma unroll
            for (int ks = 0; ks < 4; ++ks) {
                int kb = ks * 8;
                unsigned a[4];
                a[0] = fu(Ps[Rm * PSTR + kb + gc]);
                a[1] = fu(Ps[(Rm + 8) * PSTR + kb + gc]);
                a[2] = fu(Ps[Rm * PSTR + kb + 4 + gc]);
                a[3] = fu(Ps[(Rm + 8) * PSTR + kb + 4 + gc]);
                #pragma unroll
                for (int nt = 0; nt < 8; ++nt) {
                    int Dn = nw * 64 + nt * 8 + gr;
                    unsigned b[2];
                    b[0] = fu(KVs[(kb + gc) * KVSTR + Dn]);
                    b[1] = fu(KVs[(kb + 4 + gc) * KVSTR + Dn]);
                    mma_tf32(O[nt], a, b);
                }
            }
        }
    }

    if ((tid & 3) == 0) Li[srow] = lrow;
    __syncthreads();
    {
        float i0 = 1.f / Li[Rm], i1 = 1.f / Li[Rm + 8];
        #pragma unroll
        for (int nt = 0; nt < 8; ++nt) {
            int Dn = nw * 64 + nt * 8 + 2 * gc;
            float* p0 = g_AO + (size_t)(q0 + Rm) * QDIM + h * HD + Dn;
            *(float2*)p0 = make_float2(O[nt][0] * i0, O[nt][1] * i0);
            float* p1 = g_AO + (size_t)(q0 + Rm + 8) * QDIM + h * HD + Dn;
            *(float2*)p1 = make_float2(O[nt][2] * i1, O[nt][3] * i1);
        }
    }
}

// ---------------- launch ------------------------------------------------------
extern "C" void kernel_launch(void* const* d_in, const int* in_sizes, int n_in,
                              void* d_out, int out_size)
{
    const float* hs    = (const float*)d_in[0];
    const float* cos_t = (const float*)d_in[1];
    const float* sin_t = (const float*)d_in[2];
    // d_in[3] = attention_mask (causal tril; applied analytically)
    const float* wq = (const float*)d_in[4];
    const float* wk = (const float*)d_in[5];
    const float* wv = (const float*)d_in[6];
    const float* wo = (const float*)d_in[7];
    const float* qw = (const float*)d_in[8];
    const float* kw = (const float*)d_in[9];
    float* out = (float*)d_out;

    gemm_qkv_kernel<<<512, 256>>>(hs, wq, wk, wv);
    rmsnorm_rope_kernel<<<dim3(S_LEN, NH + NKV), 128>>>(cos_t, sin_t, qw, kw);
    flash_kernel<<<dim3(S_LEN / 32, NH), 128>>>();
    gemm_out_kernel<<<256, 256>>>(wo, out);
}